// round 1
// baseline (speedup 1.0000x reference)
#include <cuda_runtime.h>
#include <cuda_fp16.h>

#define S2_    4096
#define RF_    15
#define INPUT_ 48
#define ITERS_ 50

// ---------------- scratch (device globals; no runtime allocation) ----------------
__device__ __half g_W1[(size_t)S2_ * S2_];   // l4_w  = lwe - normalized(l4c*(1-masks))   (32 MB)
__device__ __half g_W2[(size_t)S2_ * S2_];   // exc_n - inh_n                              (32 MB)
__device__ float  g_aff[S2_];
__device__ float  g_cur[2][S2_];
__device__ float  g_l4[2][S2_];

// ---------------- init state to zeros (output-independent of poison) -------------
__global__ void init_state_kernel() {
    int i = blockIdx.x * blockDim.x + threadIdx.x;
    if (i < S2_) { g_cur[0][i] = 0.f; g_l4[0][i] = 0.f; }
}

// ---------------- afferent[i] = sum_{k} img[rf[i,k,0], rf[i,k,1]] * aw[i,k] ------
// one warp per sheet unit; lanes stride the 225-element RF window (coalesced).
__global__ void afferent_kernel(const float* __restrict__ img,
                                const int*   __restrict__ rf,
                                const float* __restrict__ aw) {
    int w    = (blockIdx.x * blockDim.x + threadIdx.x) >> 5;
    int lane = threadIdx.x & 31;
    if (w >= S2_) return;
    const int*   g  = rf + (size_t)w * (RF_ * RF_ * 2);
    const float* av = aw + (size_t)w * (RF_ * RF_);
    float s = 0.f;
    for (int k = lane; k < RF_ * RF_; k += 32) {
        int y = g[2 * k], x = g[2 * k + 1];
        s += img[y * INPUT_ + x] * av[k];
    }
    #pragma unroll
    for (int o = 16; o > 0; o >>= 1) s += __shfl_down_sync(0xffffffffu, s, o);
    if (lane == 0) g_aff[w] = s;
}

// ---------------- build W1 (l4_w) and W2 (exc-inh) in fp16, one block per row ----
__global__ void __launch_bounds__(256) build_kernel(const float* __restrict__ lc,
                                                    const float* __restrict__ l4c,
                                                    const float* __restrict__ lwe,
                                                    const float* __restrict__ masks) {
    const int    row  = blockIdx.x;
    const size_t base = (size_t)row * S2_;
    const int    tid  = threadIdx.x;
    const float  A = 1.5f / 4096.f, B = 1.0f / 4096.f;

    float lm[16], lcv[16];
    float s_mid = 0.f, s_exc = 0.f, s_inh = 0.f;
    #pragma unroll
    for (int k = 0; k < 16; ++k) {
        int   j = tid + k * 256;
        float m = l4c[base + j] * (1.f - masks[base + j]);
        lm[k] = m;  s_mid += m;
        float c = lc[base + j];
        lcv[k] = c;
        s_exc += fmaxf(c - A, 0.f);
        s_inh += fmaxf(c - B, 0.f);
    }
    // block reduce 3 sums
    __shared__ float sm[3][8];
    int lane = tid & 31, wid = tid >> 5;
    #pragma unroll
    for (int o = 16; o > 0; o >>= 1) {
        s_mid += __shfl_down_sync(0xffffffffu, s_mid, o);
        s_exc += __shfl_down_sync(0xffffffffu, s_exc, o);
        s_inh += __shfl_down_sync(0xffffffffu, s_inh, o);
    }
    if (lane == 0) { sm[0][wid] = s_mid; sm[1][wid] = s_exc; sm[2][wid] = s_inh; }
    __syncthreads();
    float tm = 0.f, te = 0.f, ti = 0.f;
    #pragma unroll
    for (int k = 0; k < 8; ++k) { tm += sm[0][k]; te += sm[1][k]; ti += sm[2][k]; }
    const float im = 1.f / (tm + 1e-11f);
    const float ie = 1.f / (te + 1e-11f);
    const float ii = 1.f / (ti + 1e-11f);

    #pragma unroll
    for (int k = 0; k < 16; ++k) {
        int j = tid + k * 256;
        g_W1[base + j] = __float2half(lwe[base + j] - lm[k] * im);
        g_W2[base + j] = __float2half(fmaxf(lcv[k] - A, 0.f) * ie -
                                      fmaxf(lcv[k] - B, 0.f) * ii);
    }
}

// ---------------- per-iteration fused kernel -------------------------------------
// 256 blocks x 256 threads; block owns 16 output units.
// warps 0-3: l4_lat[i] = W1[i,:] . l4_old   (4 rows/warp)
// warps 4-7: lateral[i] = W2[i,:] . cur_old (4 rows/warp)
// then fused elementwise update of 16 units.
__device__ __forceinline__ float dot8(const __half* __restrict__ w,
                                      const float4& xa, const float4& xb) {
    uint4 u = *reinterpret_cast<const uint4*>(w);
    __half2 h0 = *reinterpret_cast<const __half2*>(&u.x);
    __half2 h1 = *reinterpret_cast<const __half2*>(&u.y);
    __half2 h2 = *reinterpret_cast<const __half2*>(&u.z);
    __half2 h3 = *reinterpret_cast<const __half2*>(&u.w);
    float2 f0 = __half22float2(h0);
    float2 f1 = __half22float2(h1);
    float2 f2 = __half22float2(h2);
    float2 f3 = __half22float2(h3);
    float s = f0.x * xa.x;
    s = fmaf(f0.y, xa.y, s);
    s = fmaf(f1.x, xa.z, s);
    s = fmaf(f1.y, xa.w, s);
    s = fmaf(f2.x, xb.x, s);
    s = fmaf(f2.y, xb.y, s);
    s = fmaf(f3.x, xb.z, s);
    s = fmaf(f3.y, xb.w, s);
    return s;
}

__global__ void __launch_bounds__(256) iter_kernel(const float* __restrict__ thr,
                                                   const float* __restrict__ l4thr,
                                                   int pin, int pout,
                                                   float* __restrict__ fout) {
    __shared__ float xs_l4[S2_];
    __shared__ float xs_cur[S2_];
    __shared__ float res[2][16];

    const int tid = threadIdx.x;
    {   // cooperative load of both state vectors (16 KB each) into smem
        const float4* a  = reinterpret_cast<const float4*>(g_l4[pin]);
        const float4* b  = reinterpret_cast<const float4*>(g_cur[pin]);
        float4*       sa = reinterpret_cast<float4*>(xs_l4);
        float4*       sb = reinterpret_cast<float4*>(xs_cur);
        for (int k = tid; k < S2_ / 4; k += 256) { sa[k] = a[k]; sb[k] = b[k]; }
    }
    __syncthreads();

    const int wid  = tid >> 5;
    const int lane = tid & 31;
    const int obase = blockIdx.x * 16;
    const int sel  = (wid >= 4) ? 1 : 0;
    const __half* __restrict__ W  = sel ? g_W2 : g_W1;
    const float*  __restrict__ xs = sel ? xs_cur : xs_l4;
    const int rw = (wid & 3) * 4;

    const __half* r0 = W + (size_t)(obase + rw) * S2_;
    const __half* r1 = r0 + S2_;
    const __half* r2 = r1 + S2_;
    const __half* r3 = r2 + S2_;

    float a0 = 0.f, a1 = 0.f, a2 = 0.f, a3 = 0.f;
    #pragma unroll 4
    for (int t = 0; t < 16; ++t) {
        int j = t * 256 + lane * 8;
        float4 xa = *reinterpret_cast<const float4*>(xs + j);
        float4 xb = *reinterpret_cast<const float4*>(xs + j + 4);
        a0 += dot8(r0 + j, xa, xb);
        a1 += dot8(r1 + j, xa, xb);
        a2 += dot8(r2 + j, xa, xb);
        a3 += dot8(r3 + j, xa, xb);
    }
    #pragma unroll
    for (int o = 16; o > 0; o >>= 1) {
        a0 += __shfl_down_sync(0xffffffffu, a0, o);
        a1 += __shfl_down_sync(0xffffffffu, a1, o);
        a2 += __shfl_down_sync(0xffffffffu, a2, o);
        a3 += __shfl_down_sync(0xffffffffu, a3, o);
    }
    if (lane == 0) {
        res[sel][rw + 0] = a0;
        res[sel][rw + 1] = a1;
        res[sel][rw + 2] = a2;
        res[sel][rw + 3] = a3;
    }
    __syncthreads();

    if (tid < 16) {
        int   i      = obase + tid;
        float l4aff  = g_aff[i] * 0.5f + xs_cur[i] * 0.5f;   // b*0.5 == 0.5 to 1e-11
        float l4n    = tanhf(fmaxf(l4aff + res[0][tid] - l4thr[i], 0.f) * 2.0f);
        float curn   = tanhf(fmaxf(l4n + res[1][tid] - thr[i], 0.f));
        g_l4[pout][i] = l4n;
        if (fout) fout[i] = curn;
        else      g_cur[pout][i] = curn;
    }
}

// ---------------- launch ---------------------------------------------------------
extern "C" void kernel_launch(void* const* d_in, const int* in_sizes, int n_in,
                              void* d_out, int out_size) {
    const float* img   = (const float*)d_in[0];   // (1,1,48,48)
    const int*   rf    = (const int*)  d_in[1];   // (4096,15,15,2)
    const float* aw    = (const float*)d_in[2];   // (4096,1,15,15)
    const float* lc    = (const float*)d_in[3];   // (4096,4096)
    const float* l4c   = (const float*)d_in[4];   // (4096,4096)
    const float* lwe   = (const float*)d_in[5];   // (4096,4096)
    const float* masks = (const float*)d_in[6];   // (4096,4096)
    const float* thr   = (const float*)d_in[7];   // (1,1,64,64)
    const float* l4thr = (const float*)d_in[8];   // (1,1,64,64)
    float*       out   = (float*)d_out;           // (1,1,64,64)

    init_state_kernel<<<16, 256>>>();
    afferent_kernel<<<512, 256>>>(img, rf, aw);   // 4096 warps
    build_kernel<<<S2_, 256>>>(lc, l4c, lwe, masks);

    for (int t = 0; t < ITERS_; ++t) {
        int    pin  = t & 1;
        int    pout = (t + 1) & 1;
        float* fout = (t == ITERS_ - 1) ? out : nullptr;
        iter_kernel<<<256, 256>>>(thr, l4thr, pin, pout, fout);
    }
}